// round 13
// baseline (speedup 1.0000x reference)
#include <cuda_runtime.h>
#include <cuda_bf16.h>
#include <cstdint>

// ---------------------------------------------------------------------------
// ClusterLoss via tf32 mma.sync. 2 CTAs/SM (128-row tiles, 90.9KB smem each)
// so independent CTAs overlap load/epilogue phases with MMA phases.
// out = mean((X-dec)^2) + ALPHA * soft_kmeans_loss(enc, K=64), 10 iters.
// ---------------------------------------------------------------------------

#define NROWS   65536
#define DLAT    64
#define KC      64
#define NDATA   33554432
#define ALPHA   0.001f
#define EPSV    1e-8f

#define TROWS   128     // rows per tile
#define SE_ST   76      // sE row stride (u32): 0..63 data, 64 ones, pad
#define SC_ST   68
#define SRT_ST  132     // sRT: [cluster][row], 64 x 128 (+4 pad)

__device__ float    g_C[KC * DLAT];
__device__ float    g_RtE[KC * 72];      // col 64 = sumR
__device__ float    g_dec;
__device__ float    g_loss;
__device__ unsigned g_ticket;

// ---------------------------------------------------------------------------
__global__ void init_kernel(const float* __restrict__ enc) {
    int t = threadIdx.x;
    for (int i = t; i < KC * DLAT; i += blockDim.x) g_C[i] = enc[i];
    for (int i = t; i < KC * 72;   i += blockDim.x) g_RtE[i] = 0.f;
    if (t == 0) { g_dec = 0.f; g_loss = 0.f; g_ticket = 0u; }
}

// ---------------------------------------------------------------------------
__global__ void decoder_kernel(const float4* __restrict__ X,
                               const float4* __restrict__ Dc, int n4) {
    float s = 0.f;
    for (int i = blockIdx.x * blockDim.x + threadIdx.x; i < n4;
         i += gridDim.x * blockDim.x) {
        float4 x = __ldg(X + i);
        float4 d = __ldg(Dc + i);
        float a = x.x - d.x, b = x.y - d.y, c = x.z - d.z, w = x.w - d.w;
        s = fmaf(a, a, fmaf(b, b, fmaf(c, c, fmaf(w, w, s))));
    }
    #pragma unroll
    for (int o = 16; o; o >>= 1) s += __shfl_down_sync(0xffffffffu, s, o);
    __shared__ float ws[8];
    int lane = threadIdx.x & 31, wid = threadIdx.x >> 5;
    if (lane == 0) ws[wid] = s;
    __syncthreads();
    if (wid == 0) {
        s = (lane < 8) ? ws[lane] : 0.f;
        #pragma unroll
        for (int o = 4; o; o >>= 1) s += __shfl_down_sync(0xffffffffu, s, o);
        if (lane == 0) atomicAdd(&g_dec, s);
    }
}

// ---------------------------------------------------------------------------
__device__ __forceinline__ uint32_t f2tf(float f) {
    uint32_t u;
    asm("cvt.rna.tf32.f32 %0, %1;" : "=r"(u) : "f"(f));
    return u;
}

__device__ __forceinline__ void mma_tf32(float& d0, float& d1, float& d2, float& d3,
                                         uint32_t a0, uint32_t a1, uint32_t a2, uint32_t a3,
                                         uint32_t b0, uint32_t b1) {
    asm volatile(
        "mma.sync.aligned.m16n8k8.row.col.f32.tf32.tf32.f32 "
        "{%0,%1,%2,%3}, {%4,%5,%6,%7}, {%8,%9}, {%0,%1,%2,%3};"
        : "+f"(d0), "+f"(d1), "+f"(d2), "+f"(d3)
        : "r"(a0), "r"(a1), "r"(a2), "r"(a3), "r"(b0), "r"(b1));
}

// exp(x), x<=0, FMA-pipe only.
__device__ __forceinline__ float fexp(float x) {
    float y = x * 1.44269504f;
    y = fmaxf(y, -126.0f);
    float t = y + 12582912.0f;
    float n = t - 12582912.0f;
    float f = y - n;
    float p = 0.00961812911f;
    p = fmaf(p, f, 0.0555041087f);
    p = fmaf(p, f, 0.240226507f);
    p = fmaf(p, f, 0.693147181f);
    p = fmaf(p, f, 1.0f);
    float s = __int_as_float((__float_as_int(t) << 23) + 0x3F800000);
    return s * p;
}

// ---------------------------------------------------------------------------
// Grid = 256 CTAs x 2 tiles of 128 rows. 256 threads (8 warps), 2 CTAs/SM.
// GEMM1: warp w -> 16-row m-tile. GEMM2: warp = (mt2, n-half), full k.
extern __shared__ float s_dyn[];
__global__ void __launch_bounds__(256, 2)
iter_kernel(const float* __restrict__ enc, int is_loss) {
    float* sC  = s_dyn;                       // 64*68
    float* sC2 = sC + KC * SC_ST;             // 64
    float* sX2 = sC2 + KC;                    // 128
    float* sE  = sX2 + TROWS;                 // 128*76
    float* sRT = sE + TROWS * SE_ST;          // 64*132
    uint32_t* uC  = (uint32_t*)sC;
    uint32_t* uE  = (uint32_t*)sE;
    uint32_t* uRT = (uint32_t*)sRT;
    __shared__ float ws[8];
    __shared__ unsigned s_last;

    int t = threadIdx.x, lane = t & 31, warp = t >> 5;
    int lg = lane >> 2, lt = lane & 3;

    // C -> smem tf32, c2
    for (int i = t; i < KC * DLAT; i += 256) {
        int k = i >> 6, d = i & 63;
        uC[k * SC_ST + d] = f2tf(g_C[i]);
    }
    __syncthreads();
    if (t < KC) {
        float s = 0.f;
        #pragma unroll
        for (int d = 0; d < DLAT; d++) { float c = sC[t * SC_ST + d]; s = fmaf(c, c, s); }
        sC2[t] = s;
    }

    // GEMM2 warp roles: 4 m-tiles x 2 n-halves
    int mt2    = warp & 3;
    int nh     = warp >> 2;
    int ntbase = nh ? 5 : 0;
    int ntcnt  = nh ? 4 : 5;
    float acc2[5][4];
    #pragma unroll
    for (int j = 0; j < 5; j++)
        #pragma unroll
        for (int c = 0; c < 4; c++) acc2[j][c] = 0.f;

    float blk_loss = 0.f;
    int m0 = warp * 16;                        // GEMM1 m-tile (16 rows)

    for (int tile = 0; tile < 2; tile++) {
        __syncthreads();                       // protect sE/sRT reuse
        int row0 = (blockIdx.x * 2 + tile) * TROWS;

        // Load E tile: 2 threads per row, 32 floats each, vectorized stores.
        {
            int row = t >> 1, half = t & 1, cb = half * 32;
            const float4* ep = (const float4*)(enc + (size_t)(row0 + row) * DLAT + cb);
            uint4* dst = (uint4*)(uE + row * SE_ST + cb);
            float x2 = 0.f;
            #pragma unroll
            for (int j = 0; j < 8; j++) {
                float4 v = __ldg(ep + j);
                uint4 u;
                u.x = f2tf(v.x); u.y = f2tf(v.y); u.z = f2tf(v.z); u.w = f2tf(v.w);
                dst[j] = u;
                float f0 = __uint_as_float(u.x), f1 = __uint_as_float(u.y);
                float f2 = __uint_as_float(u.z), f3 = __uint_as_float(u.w);
                x2 = fmaf(f0, f0, fmaf(f1, f1, fmaf(f2, f2, fmaf(f3, f3, x2))));
            }
            x2 += __shfl_xor_sync(0xffffffffu, x2, 1);
            if (half == 0) sX2[row] = x2;
            else {
                uE[row * SE_ST + 64] = f2tf(1.0f);   // ones col -> sumR
                #pragma unroll
                for (int j = 65; j < SE_ST; j++) uE[row * SE_ST + j] = 0u;
            }
        }
        __syncthreads();

        // ---- GEMM1: dots = E_tile @ C^T (m=16/warp, n=64, k=64) ----
        float acc[8][4];
        #pragma unroll
        for (int nt = 0; nt < 8; nt++)
            #pragma unroll
            for (int c = 0; c < 4; c++) acc[nt][c] = 0.f;

        #pragma unroll
        for (int kt = 0; kt < 8; kt++) {
            int k0 = kt * 8;
            int r = m0 + lg;
            uint32_t a0 = uE[r * SE_ST + k0 + lt];
            uint32_t a1 = uE[(r + 8) * SE_ST + k0 + lt];
            uint32_t a2 = uE[r * SE_ST + k0 + lt + 4];
            uint32_t a3 = uE[(r + 8) * SE_ST + k0 + lt + 4];
            #pragma unroll
            for (int nt = 0; nt < 8; nt++) {
                uint32_t b0 = uC[(nt * 8 + lg) * SC_ST + k0 + lt];
                uint32_t b1 = uC[(nt * 8 + lg) * SC_ST + k0 + lt + 4];
                mma_tf32(acc[nt][0], acc[nt][1], acc[nt][2], acc[nt][3],
                         a0, a1, a2, a3, b0, b1);
            }
        }

        // ---- softmax epilogue in fragment layout ----
        #pragma unroll
        for (int h = 0; h < 2; h++) {
            int rloc = m0 + h * 8 + lg;
            float x2v = sX2[rloc];
            float vals[16];
            #pragma unroll
            for (int nt = 0; nt < 8; nt++) {
                #pragma unroll
                for (int c = 0; c < 2; c++) {
                    int col = nt * 8 + lt * 2 + c;
                    float dot = acc[nt][h * 2 + c];
                    vals[nt * 2 + c] = fmaxf(x2v + sC2[col] - 2.f * dot, 0.f);
                }
            }
            float mn = vals[0];
            #pragma unroll
            for (int j = 1; j < 16; j++) mn = fminf(mn, vals[j]);
            mn = fminf(mn, __shfl_xor_sync(0xffffffffu, mn, 1));
            mn = fminf(mn, __shfl_xor_sync(0xffffffffu, mn, 2));
            float se = 0.f, sed = 0.f;
            #pragma unroll
            for (int j = 0; j < 16; j++) {
                float ev = fexp(mn - vals[j]);
                se += ev;
                sed = fmaf(ev, vals[j], sed);
                vals[j] = ev;
            }
            se += __shfl_xor_sync(0xffffffffu, se, 1);
            se += __shfl_xor_sync(0xffffffffu, se, 2);
            if (is_loss) {
                sed += __shfl_xor_sync(0xffffffffu, sed, 1);
                sed += __shfl_xor_sync(0xffffffffu, sed, 2);
                if (lt == 0) blk_loss += sed / se;
            } else {
                float inv = 1.f / se;
                #pragma unroll
                for (int nt = 0; nt < 8; nt++) {
                    #pragma unroll
                    for (int c = 0; c < 2; c++) {
                        int col = nt * 8 + lt * 2 + c;
                        uRT[col * SRT_ST + rloc] = f2tf(vals[nt * 2 + c] * inv);
                    }
                }
            }
        }
        if (is_loss) continue;
        __syncthreads();                       // sRT ready

        // ---- GEMM2: RtE += R^T (64x128) @ [E|1] (128x72) ----
        #pragma unroll 4
        for (int kt = 0; kt < 16; kt++) {
            int k0 = kt * 8;
            int ar = mt2 * 16 + lg;
            uint32_t a0 = uRT[ar * SRT_ST + k0 + lt];
            uint32_t a1 = uRT[(ar + 8) * SRT_ST + k0 + lt];
            uint32_t a2 = uRT[ar * SRT_ST + k0 + lt + 4];
            uint32_t a3 = uRT[(ar + 8) * SRT_ST + k0 + lt + 4];
            #pragma unroll
            for (int j = 0; j < 5; j++) {
                if (j < ntcnt) {
                    int n0 = (ntbase + j) * 8;
                    uint32_t b0 = uE[(k0 + lt) * SE_ST + n0 + lg];
                    uint32_t b1 = uE[(k0 + lt + 4) * SE_ST + n0 + lg];
                    mma_tf32(acc2[j][0], acc2[j][1], acc2[j][2], acc2[j][3],
                             a0, a1, a2, a3, b0, b1);
                }
            }
        }
    }

    if (is_loss) {
        #pragma unroll
        for (int o = 16; o; o >>= 1) blk_loss += __shfl_down_sync(0xffffffffu, blk_loss, o);
        if (lane == 0) ws[warp] = blk_loss;
        __syncthreads();
        if (warp == 0) {
            blk_loss = (lane < 8) ? ws[lane] : 0.f;
            #pragma unroll
            for (int o = 4; o; o >>= 1) blk_loss += __shfl_down_sync(0xffffffffu, blk_loss, o);
            if (lane == 0) atomicAdd(&g_loss, blk_loss);
        }
        return;
    }

    // Reduce GEMM2 partials into g_RtE.
    #pragma unroll
    for (int j = 0; j < 5; j++) {
        if (j < ntcnt) {
            int n0 = (ntbase + j) * 8;
            int m  = mt2 * 16 + lg;
            int c0 = n0 + lt * 2;
            atomicAdd(&g_RtE[m * 72 + c0],           acc2[j][0]);
            atomicAdd(&g_RtE[m * 72 + c0 + 1],       acc2[j][1]);
            atomicAdd(&g_RtE[(m + 8) * 72 + c0],     acc2[j][2]);
            atomicAdd(&g_RtE[(m + 8) * 72 + c0 + 1], acc2[j][3]);
        }
    }

    // Last block updates C.
    __threadfence();
    __syncthreads();
    if (t == 0)
        s_last = (atomicAdd(&g_ticket, 1u) == (unsigned)(gridDim.x - 1)) ? 1u : 0u;
    __syncthreads();
    if (s_last) {
        __threadfence();
        for (int i = t; i < KC * DLAT; i += 256) {
            int k = i >> 6, d = i & 63;
            g_C[i] = g_RtE[k * 72 + d] / (g_RtE[k * 72 + 64] + EPSV);
        }
        __syncthreads();
        for (int i = t; i < KC * 72; i += 256) g_RtE[i] = 0.f;
        if (t == 0) g_ticket = 0u;
    }
}

// ---------------------------------------------------------------------------
__global__ void finalize_kernel(float* out) {
    out[0] = g_dec * (1.f / (float)NDATA) + ALPHA * (g_loss * (1.f / (float)NROWS));
}

// ---------------------------------------------------------------------------
extern "C" void kernel_launch(void* const* d_in, const int* in_sizes, int n_in,
                              void* d_out, int out_size) {
    const float* X   = (const float*)d_in[0];
    const float* enc = (const float*)d_in[1];
    const float* dec = (const float*)d_in[2];
    if (n_in >= 3) {
        if (in_sizes[0] == NROWS * DLAT)      { enc = (const float*)d_in[0]; X = (const float*)d_in[1]; dec = (const float*)d_in[2]; }
        else if (in_sizes[2] == NROWS * DLAT) { enc = (const float*)d_in[2]; dec = (const float*)d_in[1]; }
    }
    float* out = (float*)d_out;

    const int SMEM_F = KC * SC_ST + KC + TROWS + TROWS * SE_ST + KC * SRT_ST;
    const int SMEM_BYTES = SMEM_F * 4;   // 90880
    cudaFuncSetAttribute(iter_kernel, cudaFuncAttributeMaxDynamicSharedMemorySize, SMEM_BYTES);

    init_kernel<<<1, 256>>>(enc);
    decoder_kernel<<<2048, 256>>>((const float4*)X, (const float4*)dec, NDATA / 4);
    for (int it = 0; it < 10; it++)
        iter_kernel<<<256, 256, SMEM_BYTES>>>(enc, it == 9 ? 1 : 0);
    finalize_kernel<<<1, 1>>>(out);
}